// round 11
// baseline (speedup 1.0000x reference)
#include <cuda_runtime.h>
#include <cuda_bf16.h>
#include <cuda_fp16.h>
#include <math.h>
#include <stdint.h>

#define BATCH 2
#define SEQ   2048
#define EMB   1024
#define NH    16
#define DH    64
#define M_TOT (BATCH*SEQ)   // 4096

// ---------------------------------------------------------------------------
// Device scratch
// ---------------------------------------------------------------------------
__device__ __nv_bfloat16 g_Xhi[M_TOT*EMB];
__device__ __nv_bfloat16 g_Xlo[M_TOT*EMB];
__device__ __half        g_Xf[M_TOT*EMB];
__device__ __nv_bfloat16 g_Whi[2*EMB*EMB];   // Wq, Wk (bf16 hi)
__device__ __nv_bfloat16 g_Wlo[2*EMB*EMB];   // Wq, Wk (bf16 lo)
__device__ __half        g_Wf[2*EMB*EMB];    // Wv, Wo (single f16)
__device__ __nv_bfloat16 g_Qhi[BATCH*NH*SEQ*DH];
__device__ __nv_bfloat16 g_Qlo[BATCH*NH*SEQ*DH];
__device__ __nv_bfloat16 g_Khi[BATCH*NH*SEQ*DH];
__device__ __nv_bfloat16 g_Klo[BATCH*NH*SEQ*DH];
__device__ __half        g_Vf[BATCH*NH*SEQ*DH];   // head-major, single f16
__device__ __half        g_Of[M_TOT*EMB];         // row-major, single f16

// ---------------------------------------------------------------------------
// PTX helpers (portable sm_80-class only)
// ---------------------------------------------------------------------------
__device__ __forceinline__ uint32_t smem_u32(const void* p) {
    uint32_t a;
    asm("{ .reg .u64 t; cvta.to.shared.u64 t, %1; cvt.u32.u64 %0, t; }" : "=r"(a) : "l"(p));
    return a;
}

#define CP_ASYNC16(dst, src) \
    asm volatile("cp.async.cg.shared.global [%0], [%1], 16;" :: "r"(dst), "l"(src))
#define CP_COMMIT() asm volatile("cp.async.commit_group;")
#define CP_WAIT0()  asm volatile("cp.async.wait_group 0;")
#define CP_WAIT1()  asm volatile("cp.async.wait_group 1;")

#define LDSM4(r, addr) \
    asm volatile("ldmatrix.sync.aligned.m8n8.x4.shared.b16 {%0,%1,%2,%3}, [%4];" \
        : "=r"((r)[0]), "=r"((r)[1]), "=r"((r)[2]), "=r"((r)[3]) : "r"(addr))
#define LDSM4T(r, addr) \
    asm volatile("ldmatrix.sync.aligned.m8n8.x4.trans.shared.b16 {%0,%1,%2,%3}, [%4];" \
        : "=r"((r)[0]), "=r"((r)[1]), "=r"((r)[2]), "=r"((r)[3]) : "r"(addr))

#define MMA_BF16(c, a, b0v, b1v) \
    asm volatile("mma.sync.aligned.m16n8k16.row.col.f32.bf16.bf16.f32 " \
        "{%0,%1,%2,%3}, {%4,%5,%6,%7}, {%8,%9}, {%0,%1,%2,%3};" \
        : "+f"((c)[0]), "+f"((c)[1]), "+f"((c)[2]), "+f"((c)[3]) \
        : "r"((a)[0]), "r"((a)[1]), "r"((a)[2]), "r"((a)[3]), "r"(b0v), "r"(b1v))

#define MMA_F16(c, a, b0v, b1v) \
    asm volatile("mma.sync.aligned.m16n8k16.row.col.f32.f16.f16.f32 " \
        "{%0,%1,%2,%3}, {%4,%5,%6,%7}, {%8,%9}, {%0,%1,%2,%3};" \
        : "+f"((c)[0]), "+f"((c)[1]), "+f"((c)[2]), "+f"((c)[3]) \
        : "r"((a)[0]), "r"((a)[1]), "r"((a)[2]), "r"((a)[3]), "r"(b0v), "r"(b1v))

__device__ __forceinline__ float fast_exp2(float x) {
    float r;
    asm("ex2.approx.ftz.f32 %0, %1;" : "=f"(r) : "f"(x));
    return r;
}

__device__ __forceinline__ uint32_t packbf2(float lo, float hi) {
    uint32_t r;
    asm("cvt.rn.bf16x2.f32 %0, %1, %2;" : "=r"(r) : "f"(hi), "f"(lo));
    return r;
}
__device__ __forceinline__ float bflo(uint32_t u) { return __uint_as_float(u << 16); }
__device__ __forceinline__ float bfhi(uint32_t u) { return __uint_as_float(u & 0xFFFF0000u); }

__device__ __forceinline__ uint32_t packh2(float a, float b) {
    __half2 h = __floats2half2_rn(a, b);
    return *(uint32_t*)&h;
}
__device__ __forceinline__ float hsum2(uint32_t u) {
    __half2 h = *(__half2*)&u;
    float2 f = __half22float2(h);
    return f.x + f.y;
}

__device__ __forceinline__ uint32_t swz(uint32_t off) {   // SW128 for 128B rows
    return off ^ ((off >> 3) & 0x70);
}

// ---------------------------------------------------------------------------
// Fused conversion kernel: blocks [0,2048) convert X; [2048,2560) convert W.
// ---------------------------------------------------------------------------
__global__ void convert_all(const float* __restrict__ X,
                            const float* __restrict__ W0, const float* __restrict__ W1,
                            const float* __restrict__ W2, const float* __restrict__ W3)
{
    __shared__ float Wsm[64][129];
    const int tid = threadIdx.x;
    if (blockIdx.x < 2048) {
        int gid = blockIdx.x * 256 + tid;
        size_t base = (size_t)gid * 8;
        float4 v0 = *(const float4*)&X[base];
        float4 v1 = *(const float4*)&X[base + 4];
        float vs[8] = {v0.x, v0.y, v0.z, v0.w, v1.x, v1.y, v1.z, v1.w};
        __nv_bfloat16 h[8], l[8];
        __half f[8];
#pragma unroll
        for (int i = 0; i < 8; i++) {
            h[i] = __float2bfloat16(vs[i]);
            l[i] = __float2bfloat16(vs[i] - __bfloat162float(h[i]));
            f[i] = __float2half_rn(vs[i]);
        }
        *(uint4*)&g_Xhi[base] = *(uint4*)h;
        *(uint4*)&g_Xlo[base] = *(uint4*)l;
        *(uint4*)&g_Xf[base]  = *(uint4*)f;
        return;
    }

    int bi = blockIdx.x - 2048;          // 0..511
    int w = bi >> 7;
    int rest = bi & 127;
    int ntile = rest >> 4;
    int kc = rest & 15;
    const float* W = (w == 0) ? W0 : (w == 1) ? W1 : (w == 2) ? W2 : W3;

#pragma unroll
    for (int i = 0; i < 32; i++) {
        int lin = i * 256 + tid;
        int kr = lin >> 7;
        int nc = lin & 127;
        Wsm[kr][nc] = W[(size_t)(kc * 64 + kr) * EMB + ntile * 128 + nc];
    }
    __syncthreads();

#pragma unroll
    for (int j = 0; j < 4; j++) {
        int lin = j * 256 + tid;
        int nin = lin >> 3;
        int g = lin & 7;
        float vs[8];
#pragma unroll
        for (int i = 0; i < 8; i++) vs[i] = Wsm[g * 8 + i][nin];
        if (w < 2) {
            size_t base = ((size_t)(w * EMB + ntile * 128 + nin)) * EMB + kc * 64 + g * 8;
            __nv_bfloat16 h[8], l[8];
#pragma unroll
            for (int i = 0; i < 8; i++) {
                h[i] = __float2bfloat16(vs[i]);
                l[i] = __float2bfloat16(vs[i] - __bfloat162float(h[i]));
            }
            *(uint4*)&g_Whi[base] = *(uint4*)h;
            *(uint4*)&g_Wlo[base] = *(uint4*)l;
        } else {
            size_t base = ((size_t)((w - 2) * EMB + ntile * 128 + nin)) * EMB + kc * 64 + g * 8;
            __half h[8];
#pragma unroll
            for (int i = 0; i < 8; i++) h[i] = __float2half_rn(vs[i]);
            *(uint4*)&g_Wf[base] = *(uint4*)h;
        }
    }
}

// ---------------------------------------------------------------------------
// Merged QKV projection launch: 384 CTAs.
//   CTA [0,128):  V single-f16 GEMM (short, dispatched FIRST to fill wave 1
//                 alongside heavy QK CTAs -> uniform QK tail, better makespan)
//   CTA [128,384): bf16x3 GEMM (Q: z=0, K: z=1), CTA 256x128, 512 thr.
// ---------------------------------------------------------------------------
#define A_TILE_B 20480                   // 256 rows * 80B
#define B_TILE_B 10240                   // 128 rows * 80B
#define STAGE_QK (2*A_TILE_B + 2*B_TILE_B)   // 61440
#define STAGE_F16 (A_TILE_B + B_TILE_B)      // 30720
#define PROJ_SMEM (3*STAGE_QK)           // 184320

__global__ __launch_bounds__(512)
void proj_all()
{
    extern __shared__ __align__(128) char smem[];
    const uint32_t sb = smem_u32(smem);
    const int tid = threadIdx.x, lane = tid & 31, wid = tid >> 5;
    const int wm = wid & 3, wn = wid >> 2;

    const uint32_t aRowB = (wm * 64 + (lane & 15)) * 80;
    const uint32_t aColB = (lane >> 4) * 16;
    const uint32_t bRowB = (wn * 32 + (lane & 7) + ((lane >> 4) << 3)) * 80;
    const uint32_t bColB = ((lane >> 3) & 1) * 16;
    const int lr = tid >> 2;
    const int ls4 = tid & 3;

    float acc[4][4][4];
#pragma unroll
    for (int i = 0; i < 4; i++)
#pragma unroll
        for (int j = 0; j < 4; j++)
#pragma unroll
            for (int q = 0; q < 4; q++) acc[i][j][q] = 0.0f;

    if (blockIdx.x >= 128) {
        // ---------------- Q/K bf16x3 path ----------------
        const int qk = blockIdx.x - 128;
        const int z = qk >> 7;
        const int r = qk & 127;
        const int bx = r & 7, by = r >> 3;

        const __nv_bfloat16* Bhi = g_Whi + (size_t)z * EMB * EMB;
        const __nv_bfloat16* Blo = g_Wlo + (size_t)z * EMB * EMB;

        auto load_stage = [&](int c, int slot) {
            const int k0 = c * 32;
            const uint32_t st = sb + slot * STAGE_QK;
#pragma unroll
            for (int i = 0; i < 2; i++) {
                const int rr = i * 128 + lr;
                CP_ASYNC16(st + rr * 80 + ls4 * 16,
                           g_Xhi + (size_t)(by * 256 + rr) * EMB + k0 + ls4 * 8);
                CP_ASYNC16(st + A_TILE_B + rr * 80 + ls4 * 16,
                           g_Xlo + (size_t)(by * 256 + rr) * EMB + k0 + ls4 * 8);
            }
            CP_ASYNC16(st + 2 * A_TILE_B + lr * 80 + ls4 * 16,
                       Bhi + (size_t)(bx * 128 + lr) * EMB + k0 + ls4 * 8);
            CP_ASYNC16(st + 2 * A_TILE_B + B_TILE_B + lr * 80 + ls4 * 16,
                       Blo + (size_t)(bx * 128 + lr) * EMB + k0 + ls4 * 8);
            CP_COMMIT();
        };

        load_stage(0, 0);
        load_stage(1, 1);

        for (int c = 0; c < 32; c++) {
            CP_WAIT1();
            __syncthreads();
            if (c + 2 < 32) load_stage(c + 2, (c + 2) % 3);
            const uint32_t st = sb + (c % 3) * STAGE_QK;
            const uint32_t atH = st, atL = st + A_TILE_B;
            const uint32_t btH = st + 2 * A_TILE_B, btL = st + 2 * A_TILE_B + B_TILE_B;

#pragma unroll
            for (int kc = 0; kc < 2; kc++) {
                const uint32_t kB = kc * 32;
                uint32_t bh[2][4], bl[2][4], ar[4][4];
#pragma unroll
                for (int ni = 0; ni < 2; ni++) {
                    LDSM4(bh[ni], btH + bRowB + ni * (16 * 80) + kB + bColB);
                    LDSM4(bl[ni], btL + bRowB + ni * (16 * 80) + kB + bColB);
                }
#pragma unroll
                for (int mi = 0; mi < 4; mi++)
                    LDSM4(ar[mi], atH + aRowB + mi * (16 * 80) + kB + aColB);
#pragma unroll
                for (int mi = 0; mi < 4; mi++)
#pragma unroll
                    for (int ni = 0; ni < 2; ni++) {
                        MMA_BF16(acc[mi][2 * ni],     ar[mi], bh[ni][0], bh[ni][1]);
                        MMA_BF16(acc[mi][2 * ni + 1], ar[mi], bh[ni][2], bh[ni][3]);
                        MMA_BF16(acc[mi][2 * ni],     ar[mi], bl[ni][0], bl[ni][1]);
                        MMA_BF16(acc[mi][2 * ni + 1], ar[mi], bl[ni][2], bl[ni][3]);
                    }
#pragma unroll
                for (int mi = 0; mi < 4; mi++)
                    LDSM4(ar[mi], atL + aRowB + mi * (16 * 80) + kB + aColB);
#pragma unroll
                for (int mi = 0; mi < 4; mi++)
#pragma unroll
                    for (int ni = 0; ni < 2; ni++) {
                        MMA_BF16(acc[mi][2 * ni],     ar[mi], bh[ni][0], bh[ni][1]);
                        MMA_BF16(acc[mi][2 * ni + 1], ar[mi], bh[ni][2], bh[ni][3]);
                    }
            }
        }
        __syncthreads();   // before smem reuse by epilogue

        float* Cs = (float*)smem;            // [256][132]
#pragma unroll
        for (int mi = 0; mi < 4; mi++)
#pragma unroll
            for (int nf = 0; nf < 4; nf++) {
                const int row0 = wm * 64 + mi * 16 + (lane >> 2);
                const int col  = wn * 32 + nf * 8 + (lane & 3) * 2;
                *(float2*)&Cs[row0 * 132 + col]       = make_float2(acc[mi][nf][0], acc[mi][nf][1]);
                *(float2*)&Cs[(row0 + 8) * 132 + col] = make_float2(acc[mi][nf][2], acc[mi][nf][3]);
            }
        __syncthreads();

#pragma unroll
        for (int it = 0; it < 16; it++) {
            const int lin = it * 512 + tid;
            const int rr = lin >> 5;
            const int cg = (lin & 31) * 4;
            float4 v = *(const float4*)&Cs[rr * 132 + cg];
            const int m = by * 256 + rr;
            const int n = bx * 128 + cg;
            const int b = m >> 11, s = m & 2047, h = n >> 6, d = n & 63;
            __nv_bfloat16* dh = (z == 0) ? g_Qhi : g_Khi;
            __nv_bfloat16* dl = (z == 0) ? g_Qlo : g_Klo;
            uint32_t u0 = packbf2(v.x, v.y), u1 = packbf2(v.z, v.w);
            uint32_t l0 = packbf2(v.x - bflo(u0), v.y - bfhi(u0));
            uint32_t l1 = packbf2(v.z - bflo(u1), v.w - bfhi(u1));
            size_t addr = (((size_t)(b * NH + h)) * SEQ + s) * DH + d;
            *(uint2*)&dh[addr] = make_uint2(u0, u1);
            *(uint2*)&dl[addr] = make_uint2(l0, l1);
        }
    } else {
        // ---------------- V single-f16 path (dispatched first) ----------------
        const int j = blockIdx.x;
        const int bx = j & 7, by = j >> 3;
        const __half* Bf = g_Wf;                  // Wv

        auto load_stage = [&](int c, int slot) {
            const int k0 = c * 32;
            const uint32_t st = sb + slot * STAGE_F16;
#pragma unroll
            for (int i = 0; i < 2; i++) {
                const int rr = i * 128 + lr;
                CP_ASYNC16(st + rr * 80 + ls4 * 16,
                           g_Xf + (size_t)(by * 256 + rr) * EMB + k0 + ls4 * 8);
            }
            CP_ASYNC16(st + A_TILE_B + lr * 80 + ls4 * 16,
                       Bf + (size_t)(bx * 128 + lr) * EMB + k0 + ls4 * 8);
            CP_COMMIT();
        };

        load_stage(0, 0);
        load_stage(1, 1);

        for (int c = 0; c < 32; c++) {
            CP_WAIT1();
            __syncthreads();
            if (c + 2 < 32) load_stage(c + 2, (c + 2) % 3);
            const uint32_t st = sb + (c % 3) * STAGE_F16;
            const uint32_t at = st, bt = st + A_TILE_B;

#pragma unroll
            for (int kc = 0; kc < 2; kc++) {
                const uint32_t kB = kc * 32;
                uint32_t bh[2][4], ar[4][4];
#pragma unroll
                for (int ni = 0; ni < 2; ni++)
                    LDSM4(bh[ni], bt + bRowB + ni * (16 * 80) + kB + bColB);
#pragma unroll
                for (int mi = 0; mi < 4; mi++)
                    LDSM4(ar[mi], at + aRowB + mi * (16 * 80) + kB + aColB);
#pragma unroll
                for (int mi = 0; mi < 4; mi++)
#pragma unroll
                    for (int ni = 0; ni < 2; ni++) {
                        MMA_F16(acc[mi][2 * ni],     ar[mi], bh[ni][0], bh[ni][1]);
                        MMA_F16(acc[mi][2 * ni + 1], ar[mi], bh[ni][2], bh[ni][3]);
                    }
            }
        }
        __syncthreads();

        float* Cs = (float*)smem;            // [256][132]
#pragma unroll
        for (int mi = 0; mi < 4; mi++)
#pragma unroll
            for (int nf = 0; nf < 4; nf++) {
                const int row0 = wm * 64 + mi * 16 + (lane >> 2);
                const int col  = wn * 32 + nf * 8 + (lane & 3) * 2;
                *(float2*)&Cs[row0 * 132 + col]       = make_float2(acc[mi][nf][0], acc[mi][nf][1]);
                *(float2*)&Cs[(row0 + 8) * 132 + col] = make_float2(acc[mi][nf][2], acc[mi][nf][3]);
            }
        __syncthreads();

#pragma unroll
        for (int it = 0; it < 16; it++) {
            const int lin = it * 512 + tid;
            const int rr = lin >> 5;
            const int cg = (lin & 31) * 4;
            float4 v = *(const float4*)&Cs[rr * 132 + cg];
            const int m = by * 256 + rr;
            const int n = bx * 128 + cg;
            const int b = m >> 11, s = m & 2047, h = n >> 6, d = n & 63;
            size_t addr = (((size_t)(b * NH + h)) * SEQ + s) * DH + d;
            *(uint2*)&g_Vf[addr] = make_uint2(packh2(v.x, v.y), packh2(v.z, v.w));
        }
    }
}

// ---------------------------------------------------------------------------
// gemm_o: single-f16 GEMM, O = Of * Wo -> fp32 out. CTA 256x128, 512 thr.
// BK=64 (144B padded rows, 16 chunks), single sync per iteration.
// ---------------------------------------------------------------------------
#define O_A_TILE 36864    // 256 rows * 144B
#define O_B_TILE 18432    // 128 rows * 144B
#define O_STAGE  (O_A_TILE + O_B_TILE)   // 55296
#define GO_SMEM  (3*O_STAGE)             // 165888

__global__ __launch_bounds__(512)
void gemm_o(float* __restrict__ Cout)
{
    extern __shared__ __align__(128) char smem[];
    const uint32_t sb = smem_u32(smem);
    const int tid = threadIdx.x, lane = tid & 31, wid = tid >> 5;
    const int wm = wid & 3, wn = wid >> 2;
    const int bx = blockIdx.x, by = blockIdx.y;

    const __half* Bf = g_Wf + (size_t)EMB * EMB;   // Wo

    float acc[4][4][4];
#pragma unroll
    for (int i = 0; i < 4; i++)
#pragma unroll
        for (int j = 0; j < 4; j++)
#pragma unroll
            for (int q = 0; q < 4; q++) acc[i][j][q] = 0.0f;

    const int seg = tid & 7;
    const int row0 = tid >> 3;

    auto load_stage = [&](int c, int slot) {
        const int k0 = c * 64;
        const uint32_t st = sb + slot * O_STAGE;
#pragma unroll
        for (int i = 0; i < 4; i++) {
            const int r = i * 64 + row0;
            CP_ASYNC16(st + r * 144 + seg * 16,
                       g_Of + (size_t)(by * 256 + r) * EMB + k0 + seg * 8);
        }
#pragma unroll
        for (int i = 0; i < 2; i++) {
            const int r = i * 64 + row0;
            CP_ASYNC16(st + O_A_TILE + r * 144 + seg * 16,
                       Bf + (size_t)(bx * 128 + r) * EMB + k0 + seg * 8);
        }
        CP_COMMIT();
    };

    load_stage(0, 0);
    load_stage(1, 1);

    const uint32_t aRowB = (wm * 64 + (lane & 15)) * 144;
    const uint32_t aColB = (lane >> 4) * 16;
    const uint32_t bRowB = (wn * 32 + (lane & 7) + ((lane >> 4) << 3)) * 144;
    const uint32_t bColB = ((lane >> 3) & 1) * 16;

    for (int c = 0; c < 16; c++) {
        CP_WAIT1();
        __syncthreads();
        if (c + 2 < 16) load_stage(c + 2, (c + 2) % 3);
        const uint32_t st = sb + (c % 3) * O_STAGE;
        const uint32_t at = st, bt = st + O_A_TILE;

#pragma unroll
        for (int kc = 0; kc < 4; kc++) {
            const uint32_t kB = kc * 32;
            uint32_t bh[2][4], ar[4][4];
#pragma unroll
            for (int ni = 0; ni < 2; ni++)
                LDSM4(bh[ni], bt + bRowB + ni * (16 * 144) + kB + bColB);
#pragma unroll
            for (int mi = 0; mi < 4; mi++)
                LDSM4(ar[mi], at + aRowB + mi * (16 * 144) + kB + aColB);
#pragma unroll
            for (int mi = 0; mi < 4; mi++)
#pragma unroll
                for (int ni = 0; ni < 2; ni++) {
                    MMA_F16(acc[mi][2 * ni],     ar[mi], bh[ni][0], bh[ni][1]);
                    MMA_F16(acc[mi][2 * ni + 1], ar[mi], bh[ni][2], bh[ni][3]);
                }
        }
    }
    __syncthreads();

    float* Cs = (float*)smem;            // [256][132]
#pragma unroll
    for (int mi = 0; mi < 4; mi++)
#pragma unroll
        for (int nf = 0; nf < 4; nf++) {
            const int r0 = wm * 64 + mi * 16 + (lane >> 2);
            const int col = wn * 32 + nf * 8 + (lane & 3) * 2;
            *(float2*)&Cs[r0 * 132 + col]       = make_float2(acc[mi][nf][0], acc[mi][nf][1]);
            *(float2*)&Cs[(r0 + 8) * 132 + col] = make_float2(acc[mi][nf][2], acc[mi][nf][3]);
        }
    __syncthreads();

#pragma unroll
    for (int it = 0; it < 16; it++) {
        const int lin = it * 512 + tid;
        const int rr = lin >> 5;
        const int cg = (lin & 31) * 4;
        float4 v = *(const float4*)&Cs[rr * 132 + cg];
        const int m = by * 256 + rr;
        const int n = bx * 128 + cg;
        *(float4*)&Cout[(size_t)m * EMB + n] = v;
    }
}

// ---------------------------------------------------------------------------
// Flash attention: QK bf16x3, PV f16 P x f16 V (l over rounded P).
// Single __syncthreads per kv-iteration; ex2.approx softmax.
// ---------------------------------------------------------------------------
#define KV_STAGE 49152      // Kh 16KB + Kl 16KB + Vf 16KB
#define FL_SMEM (32768 + 2*KV_STAGE)   // 131072
#define CEXP 0.18033688f    // 0.125 * log2(e)

__global__ __launch_bounds__(256, 1)
void flash_mma()
{
    const int qi = (int)gridDim.x - 1 - blockIdx.x;   // heavy tiles first
    const int h = blockIdx.y, b = blockIdx.z;
    const int tid = threadIdx.x, lane = tid & 31, w = tid >> 5;
    extern __shared__ __align__(128) char smf[];
    const uint32_t sb = smem_u32(smf);
    const uint32_t Qh_ = sb, Ql_ = sb + 16384;

    const size_t head = ((size_t)(b * NH + h)) * SEQ * DH;
    const __nv_bfloat16* Qhg = g_Qhi + head;
    const __nv_bfloat16* Qlg = g_Qlo + head;
    const __nv_bfloat16* Khg = g_Khi + head;
    const __nv_bfloat16* Klg = g_Klo + head;
    const __half*        Vfg = g_Vf  + head;
    const int qbase = qi * 128;

#pragma unroll
    for (int i = 0; i < 4; i++) {
        int lin = i * 256 + tid;
        int r = lin >> 3, c = lin & 7;
        uint32_t off = swz(r * 128 + c * 16);
        CP_ASYNC16(Qh_ + off, Qhg + (size_t)(qbase + r) * 64 + c * 8);
        CP_ASYNC16(Ql_ + off, Qlg + (size_t)(qbase + r) * 64 + c * 8);
    }
    CP_COMMIT();

    auto load_kv = [&](int jt, int slot) {
        const uint32_t st = sb + 32768 + slot * KV_STAGE;
#pragma unroll
        for (int i = 0; i < 4; i++) {
            int lin = i * 256 + tid;
            int r = lin >> 3, c = lin & 7;
            uint32_t off = swz(r * 128 + c * 16);
            size_t gidx = (size_t)(jt * 128 + r) * 64 + c * 8;
            CP_ASYNC16(st + off,             Khg + gidx);
            CP_ASYNC16(st + 16384 + off,     Klg + gidx);
            CP_ASYNC16(st + 32768 + off,     Vfg + gidx);
        }
        CP_COMMIT();
    };

    load_kv(0, 0);
    CP_WAIT1();
    __syncthreads();

    uint32_t qh[4][4], ql[4][4];
    const uint32_t qoff = (w * 16 + (lane & 15)) * 128 + (lane >> 4) * 16;
#pragma unroll
    for (int kc = 0; kc < 4; kc++) {
        LDSM4(qh[kc], Qh_ + swz(qoff + kc * 32));
        LDSM4(ql[kc], Ql_ + swz(qoff + kc * 32));
    }

    float o_[8][4];
#pragma unroll
    for (int i = 0; i < 8; i++)
#pragma unroll
        for (int j = 0; j < 4; j++) o_[i][j] = 0.0f;
    float mrow[2] = {-3e38f, -3e38f};
    float lrow[2] = {0.0f, 0.0f};

    const int rA = qbase + w * 16 + (lane >> 2);
    const int rB = rA + 8;
    const uint32_t kOffBase = ((lane & 7) + ((lane >> 4) << 3)) * 128 + ((lane >> 3) & 1) * 16;
    const uint32_t vOffBase = (lane & 15) * 128 + (lane >> 4) * 16;

    for (int jt = 0; jt <= qi; jt++) {
        CP_WAIT0();
        __syncthreads();
        if (jt < qi) load_kv(jt + 1, (jt + 1) & 1);
        const uint32_t st = sb + 32768 + (jt & 1) * KV_STAGE;
        const uint32_t Kh_ = st, Kl_ = st + 16384, Vf_ = st + 32768;

        float s_[16][4];
#pragma unroll
        for (int i = 0; i < 16; i++)
#pragma unroll
            for (int j = 0; j < 4; j++) s_[i][j] = 0.0f;

#pragma unroll
        for (int tp = 0; tp < 4; tp++) {
#pragma unroll
            for (int kc = 0; kc < 4; kc++) {
                const uint32_t addrA = swz((2*tp)   * 16 * 128 + kOffBase + kc * 32);
                const uint32_t addrB = swz((2*tp+1) * 16 * 128 + kOffBase + kc * 32);
                uint32_t bha[4], bla[4], bhb[4], blb[4];
                LDSM4(bha, Kh_ + addrA);
                LDSM4(bhb, Kh_ + addrB);
                LDSM4(bla, Kl_ + addrA);
                LDSM4(blb, Kl_ + addrB);
                MMA_BF16(s_[4*tp],     qh[kc], bha[0], bha[1]);
                MMA_BF16(s_[4*tp + 1], qh[kc], bha[2], bha[3]);
                MMA_BF16(s_[4*tp + 2], qh[kc], bhb[0], bhb[1]);
                MMA_BF16(s_[4*tp + 3], qh[kc], bhb[2], bhb[3]);
                MMA_BF16(s_[4*tp],     ql[kc], bha[0], bha[1]);
                MMA_BF16(s_[4*tp + 1], ql[kc], bha[2], bha[3]);
                MMA_BF16(s_[4*tp + 2], ql[kc], bhb[0], bhb[1]);
                MMA_BF16(s_[4*tp + 3], ql[kc], bhb[2], bhb[3]);
                MMA_BF16(s_[4*tp],     qh[kc], bla[0], bla[1]);
                MMA_BF16(s_[4*tp + 1], qh[kc], bla[2], bla[3]);
                MMA_BF16(s_[4*tp + 2], qh[kc], blb[0], blb[1]);
                MMA_BF16(s_[4*tp + 3], qh[kc], blb[2], blb[3]);
            }
        }

        if (jt == qi) {
#pragma unroll
            for (int nf = 0; nf < 16; nf++) {
                const int colg = jt * 128 + nf * 8 + (lane & 3) * 2;
                if (colg     > rA) s_[nf][0] = -3e38f;
                if (colg + 1 > rA) s_[nf][1] = -3e38f;
                if (colg     > rB) s_[nf][2] = -3e38f;
                if (colg + 1 > rB) s_[nf][3] = -3e38f;
            }
        }

        float mx0 = -3e38f, mx1 = -3e38f;
#pragma unroll
        for (int nf = 0; nf < 16; nf++) {
            mx0 = fmaxf(mx0, fmaxf(s_[nf][0], s_[nf][1]));
            mx1 = fmaxf(mx1, fmaxf(s_[nf][2], s_[nf][3]));
        }
        mx0 = fmaxf(mx0, __shfl_xor_sync(0xffffffffu, mx0, 1));
        mx0 = fmaxf(mx0, __shfl_xor_sync(0xffffffffu, mx0, 2));
        mx1 = fmaxf(mx1, __shfl_xor_sync(0xffffffffu, mx1, 1));
        mx1 = fmaxf(mx1, __shfl_xor_sync(0xffffffffu, mx1, 2));
        const float mn0 = fmaxf(mrow[0], mx0);
        const float mn1 = fmaxf(mrow[1], mx1);
        const float c0 = fast_exp2((mrow[0] - mn0) * CEXP);
        const float c1 = fast_exp2((mrow[1] - mn1) * CEXP);
        mrow[0] = mn0; mrow[1] = mn1;

        uint32_t ph[8][4];
        float rs0 = 0.0f, rs1 = 0.0f;
#pragma unroll
        for (int j = 0; j < 8; j++) {
            const float p00 = fast_exp2((s_[2*j][0]   - mn0) * CEXP);
            const float p01 = fast_exp2((s_[2*j][1]   - mn0) * CEXP);
            const float p10 = fast_exp2((s_[2*j][2]   - mn1) * CEXP);
            const float p11 = fast_exp2((s_[2*j][3]   - mn1) * CEXP);
            const float p20 = fast_exp2((s_[2*j+1][0] - mn0) * CEXP);
            const float p21 = fast_exp2((s_[2*j+1][1] - mn0) * CEXP);
            const float p30 = fast_exp2((s_[2*j+1][2] - mn1) * CEXP);
            const float p31 = fast_exp2((s_[2*j+1][3] - mn1) * CEXP);
            ph[j][0] = packh2(p00, p01);
            ph[j][1] = packh2(p10, p11);
            ph[j][2] = packh2(p20, p21);
            ph[j][3] = packh2(p30, p31);
            rs0 += hsum2(ph[j][0]) + hsum2(ph[j][2]);
            rs1 += hsum2(ph[j][1]) + hsum2(ph[j][3]);
        }
        rs0 += __shfl_xor_sync(0xffffffffu, rs0, 1);
        rs0 += __shfl_xor_sync(0xffffffffu, rs0, 2);
        rs1 += __shfl_xor_sync(0xffffffffu, rs1, 1);
        rs1 += __shfl_xor_sync(0xffffffffu, rs1, 2);
        lrow[0] = lrow[0] * c0 + rs0;
        lrow[1] = lrow[1] * c1 + rs1;
#pragma unroll
        for (int nf = 0; nf < 8; nf++) {
            o_[nf][0] *= c0; o_[nf][1] *= c0;
            o_[nf][2] *= c1; o_[nf][3] *= c1;
        }

#pragma unroll
        for (int j = 0; j < 8; j++) {
#pragma unroll
            for (int t = 0; t < 4; t++) {
                uint32_t vf[4];
                LDSM4T(vf, Vf_ + swz(j * 16 * 128 + vOffBase + t * 32));
                MMA_F16(o_[2 * t],     ph[j], vf[0], vf[1]);
                MMA_F16(o_[2 * t + 1], ph[j], vf[2], vf[3]);
            }
        }
    }

    const float iA = 1.0f / lrow[0];
    const float iB = 1.0f / lrow[1];
    const size_t rowA = (size_t)(b * SEQ + rA) * EMB + h * 64;
    const size_t rowB = (size_t)(b * SEQ + rB) * EMB + h * 64;
#pragma unroll
    for (int nf = 0; nf < 8; nf++) {
        const int d = nf * 8 + (lane & 3) * 2;
        *(uint32_t*)&g_Of[rowA + d] = packh2(o_[nf][0] * iA, o_[nf][1] * iA);
        *(uint32_t*)&g_Of[rowB + d] = packh2(o_[nf][2] * iB, o_[nf][3] * iB);
    }
}

// ---------------------------------------------------------------------------
extern "C" void kernel_launch(void* const* d_in, const int* in_sizes, int n_in,
                              void* d_out, int out_size)
{
    const float* x  = (const float*)d_in[0];
    const float* Wq = (const float*)d_in[1];
    const float* Wk = (const float*)d_in[2];
    const float* Wv = (const float*)d_in[3];
    const float* Wo = (const float*)d_in[4];
    float* out = (float*)d_out;

    cudaFuncSetAttribute(proj_all,
                         cudaFuncAttributeMaxDynamicSharedMemorySize, PROJ_SMEM);
    cudaFuncSetAttribute(gemm_o,
                         cudaFuncAttributeMaxDynamicSharedMemorySize, GO_SMEM);
    cudaFuncSetAttribute(flash_mma,
                         cudaFuncAttributeMaxDynamicSharedMemorySize, FL_SMEM);

    // Convert X (bf16 hi/lo + f16) and W (Wq/Wk bf16 hi/lo, Wv/Wo f16)
    convert_all<<<2560, 256>>>(x, Wq, Wk, Wv, Wo);

    // V (f16, dispatched first) + Q,K (bf16x3) projections in one launch
    proj_all<<<384, 512, PROJ_SMEM>>>();

    // Flash attention -> Of (f16 row-major)
    flash_mma<<<dim3(SEQ/128, NH, BATCH), 256, FL_SMEM>>>();

    // Output projection (single f16) -> fp32 out
    gemm_o<<<dim3(8, 16), 512, GO_SMEM>>>(out);
}

// round 12
// speedup vs baseline: 1.1311x; 1.1311x over previous
#include <cuda_runtime.h>
#include <cuda_bf16.h>
#include <cuda_fp16.h>
#include <math.h>
#include <stdint.h>

#define BATCH 2
#define SEQ   2048
#define EMB   1024
#define NH    16
#define DH    64
#define M_TOT (BATCH*SEQ)   // 4096

// ---------------------------------------------------------------------------
// Device scratch
// ---------------------------------------------------------------------------
__device__ __nv_bfloat16 g_Xhi[M_TOT*EMB];
__device__ __nv_bfloat16 g_Xlo[M_TOT*EMB];
__device__ __half        g_Xf[M_TOT*EMB];
__device__ __nv_bfloat16 g_Whi[2*EMB*EMB];   // Wq, Wk (bf16 hi)
__device__ __nv_bfloat16 g_Wlo[2*EMB*EMB];   // Wq, Wk (bf16 lo)
__device__ __half        g_Wf[2*EMB*EMB];    // Wv, Wo (single f16)
__device__ __nv_bfloat16 g_Qhi[BATCH*NH*SEQ*DH];
__device__ __nv_bfloat16 g_Qlo[BATCH*NH*SEQ*DH];
__device__ __nv_bfloat16 g_Khi[BATCH*NH*SEQ*DH];
__device__ __nv_bfloat16 g_Klo[BATCH*NH*SEQ*DH];
__device__ __half        g_Vf[BATCH*NH*SEQ*DH];   // head-major, single f16
__device__ __half        g_Of[M_TOT*EMB];         // row-major, single f16

// ---------------------------------------------------------------------------
// PTX helpers (portable sm_80-class only)
// ---------------------------------------------------------------------------
__device__ __forceinline__ uint32_t smem_u32(const void* p) {
    uint32_t a;
    asm("{ .reg .u64 t; cvta.to.shared.u64 t, %1; cvt.u32.u64 %0, t; }" : "=r"(a) : "l"(p));
    return a;
}

#define CP_ASYNC16(dst, src) \
    asm volatile("cp.async.cg.shared.global [%0], [%1], 16;" :: "r"(dst), "l"(src))
#define CP_COMMIT() asm volatile("cp.async.commit_group;")
#define CP_WAIT0()  asm volatile("cp.async.wait_group 0;")
#define CP_WAIT1()  asm volatile("cp.async.wait_group 1;")

#define LDSM4(r, addr) \
    asm volatile("ldmatrix.sync.aligned.m8n8.x4.shared.b16 {%0,%1,%2,%3}, [%4];" \
        : "=r"((r)[0]), "=r"((r)[1]), "=r"((r)[2]), "=r"((r)[3]) : "r"(addr))
#define LDSM4T(r, addr) \
    asm volatile("ldmatrix.sync.aligned.m8n8.x4.trans.shared.b16 {%0,%1,%2,%3}, [%4];" \
        : "=r"((r)[0]), "=r"((r)[1]), "=r"((r)[2]), "=r"((r)[3]) : "r"(addr))

#define MMA_BF16(c, a, b0v, b1v) \
    asm volatile("mma.sync.aligned.m16n8k16.row.col.f32.bf16.bf16.f32 " \
        "{%0,%1,%2,%3}, {%4,%5,%6,%7}, {%8,%9}, {%0,%1,%2,%3};" \
        : "+f"((c)[0]), "+f"((c)[1]), "+f"((c)[2]), "+f"((c)[3]) \
        : "r"((a)[0]), "r"((a)[1]), "r"((a)[2]), "r"((a)[3]), "r"(b0v), "r"(b1v))

#define MMA_F16(c, a, b0v, b1v) \
    asm volatile("mma.sync.aligned.m16n8k16.row.col.f32.f16.f16.f32 " \
        "{%0,%1,%2,%3}, {%4,%5,%6,%7}, {%8,%9}, {%0,%1,%2,%3};" \
        : "+f"((c)[0]), "+f"((c)[1]), "+f"((c)[2]), "+f"((c)[3]) \
        : "r"((a)[0]), "r"((a)[1]), "r"((a)[2]), "r"((a)[3]), "r"(b0v), "r"(b1v))

__device__ __forceinline__ float fast_exp2(float x) {
    float r;
    asm("ex2.approx.ftz.f32 %0, %1;" : "=f"(r) : "f"(x));
    return r;
}

__device__ __forceinline__ uint32_t packbf2(float lo, float hi) {
    uint32_t r;
    asm("cvt.rn.bf16x2.f32 %0, %1, %2;" : "=r"(r) : "f"(hi), "f"(lo));
    return r;
}
__device__ __forceinline__ float bflo(uint32_t u) { return __uint_as_float(u << 16); }
__device__ __forceinline__ float bfhi(uint32_t u) { return __uint_as_float(u & 0xFFFF0000u); }

__device__ __forceinline__ uint32_t packh2(float a, float b) {
    __half2 h = __floats2half2_rn(a, b);
    return *(uint32_t*)&h;
}
__device__ __forceinline__ float hsum2(uint32_t u) {
    __half2 h = *(__half2*)&u;
    float2 f = __half22float2(h);
    return f.x + f.y;
}

__device__ __forceinline__ uint32_t swz(uint32_t off) {   // SW128 for 128B rows
    return off ^ ((off >> 3) & 0x70);
}

// ---------------------------------------------------------------------------
// Fused conversion kernel: blocks [0,2048) convert X; [2048,2560) convert W.
// ---------------------------------------------------------------------------
__global__ void convert_all(const float* __restrict__ X,
                            const float* __restrict__ W0, const float* __restrict__ W1,
                            const float* __restrict__ W2, const float* __restrict__ W3)
{
    __shared__ float Wsm[64][129];
    const int tid = threadIdx.x;
    if (blockIdx.x < 2048) {
        int gid = blockIdx.x * 256 + tid;
        size_t base = (size_t)gid * 8;
        float4 v0 = *(const float4*)&X[base];
        float4 v1 = *(const float4*)&X[base + 4];
        float vs[8] = {v0.x, v0.y, v0.z, v0.w, v1.x, v1.y, v1.z, v1.w};
        __nv_bfloat16 h[8], l[8];
        __half f[8];
#pragma unroll
        for (int i = 0; i < 8; i++) {
            h[i] = __float2bfloat16(vs[i]);
            l[i] = __float2bfloat16(vs[i] - __bfloat162float(h[i]));
            f[i] = __float2half_rn(vs[i]);
        }
        *(uint4*)&g_Xhi[base] = *(uint4*)h;
        *(uint4*)&g_Xlo[base] = *(uint4*)l;
        *(uint4*)&g_Xf[base]  = *(uint4*)f;
        return;
    }

    int bi = blockIdx.x - 2048;          // 0..511
    int w = bi >> 7;
    int rest = bi & 127;
    int ntile = rest >> 4;
    int kc = rest & 15;
    const float* W = (w == 0) ? W0 : (w == 1) ? W1 : (w == 2) ? W2 : W3;

#pragma unroll
    for (int i = 0; i < 32; i++) {
        int lin = i * 256 + tid;
        int kr = lin >> 7;
        int nc = lin & 127;
        Wsm[kr][nc] = W[(size_t)(kc * 64 + kr) * EMB + ntile * 128 + nc];
    }
    __syncthreads();

#pragma unroll
    for (int j = 0; j < 4; j++) {
        int lin = j * 256 + tid;
        int nin = lin >> 3;
        int g = lin & 7;
        float vs[8];
#pragma unroll
        for (int i = 0; i < 8; i++) vs[i] = Wsm[g * 8 + i][nin];
        if (w < 2) {
            size_t base = ((size_t)(w * EMB + ntile * 128 + nin)) * EMB + kc * 64 + g * 8;
            __nv_bfloat16 h[8], l[8];
#pragma unroll
            for (int i = 0; i < 8; i++) {
                h[i] = __float2bfloat16(vs[i]);
                l[i] = __float2bfloat16(vs[i] - __bfloat162float(h[i]));
            }
            *(uint4*)&g_Whi[base] = *(uint4*)h;
            *(uint4*)&g_Wlo[base] = *(uint4*)l;
        } else {
            size_t base = ((size_t)((w - 2) * EMB + ntile * 128 + nin)) * EMB + kc * 64 + g * 8;
            __half h[8];
#pragma unroll
            for (int i = 0; i < 8; i++) h[i] = __float2half_rn(vs[i]);
            *(uint4*)&g_Wf[base] = *(uint4*)h;
        }
    }
}

// ---------------------------------------------------------------------------
// Merged QKV projection: 768 CTAs, 256 thr, CTA tile 128x128, BK=64,
// SW128-swizzled 128B smem rows (conflict-free ldmatrix), 3-stage cp.async.
//   CTA [0,512):   bf16x3 (Q: z=0, K: z=1)
//   CTA [512,768): single-f16 V
// Warp layout 4m x 2n: warp tile 32x64.
// ---------------------------------------------------------------------------
#define PA_TILE 16384                    // 128 rows * 128B
#define PSTAGE_QK (4*PA_TILE)            // 65536 (Ah, Al, Bh, Bl)
#define PSTAGE_V  (2*PA_TILE)            // 32768 (A, B)
#define PROJ_SMEM (3*PSTAGE_QK)          // 196608

__global__ __launch_bounds__(256, 1)
void proj_all()
{
    extern __shared__ __align__(128) char smem[];
    const uint32_t sb = smem_u32(smem);
    const int tid = threadIdx.x, lane = tid & 31, wid = tid >> 5;
    const int wm = wid & 3, wn = wid >> 2;        // 4m x 2n

    // ldmatrix per-lane base offsets (pre-swizzle)
    const uint32_t aBase = (wm * 32 + (lane & 15)) * 128 + (lane >> 4) * 16;
    const uint32_t bBase = (wn * 64 + (lane & 7) + ((lane >> 4) << 3)) * 128
                         + ((lane >> 3) & 1) * 16;
    const int lrow = tid >> 3;          // 0..31 (row group per load iter)
    const int lseg = tid & 7;           // 16B segment in 128B row

    float acc[2][8][4];
#pragma unroll
    for (int i = 0; i < 2; i++)
#pragma unroll
        for (int j = 0; j < 8; j++)
#pragma unroll
            for (int q = 0; q < 4; q++) acc[i][j][q] = 0.0f;

    if (blockIdx.x < 512) {
        // ---------------- Q/K bf16x3 path ----------------
        const int z = blockIdx.x >> 8;
        const int r = blockIdx.x & 255;
        const int bx = r & 7, by = r >> 3;          // by 0..31

        const __nv_bfloat16* Bhi = g_Whi + (size_t)z * EMB * EMB;
        const __nv_bfloat16* Blo = g_Wlo + (size_t)z * EMB * EMB;

        auto load_stage = [&](int c, int slot) {
            const int k0 = c * 64;
            const uint32_t st = sb + slot * PSTAGE_QK;
#pragma unroll
            for (int i = 0; i < 4; i++) {
                const int rr = i * 32 + lrow;
                const uint32_t d = swz(rr * 128 + lseg * 16);
                const size_t gi = (size_t)(by * 128 + rr) * EMB + k0 + lseg * 8;
                const size_t gw = (size_t)(bx * 128 + rr) * EMB + k0 + lseg * 8;
                CP_ASYNC16(st + d,               g_Xhi + gi);
                CP_ASYNC16(st + PA_TILE + d,     g_Xlo + gi);
                CP_ASYNC16(st + 2*PA_TILE + d,   Bhi + gw);
                CP_ASYNC16(st + 3*PA_TILE + d,   Blo + gw);
            }
            CP_COMMIT();
        };

        load_stage(0, 0);
        load_stage(1, 1);

        for (int c = 0; c < 16; c++) {
            CP_WAIT1();
            __syncthreads();
            if (c + 2 < 16) load_stage(c + 2, (c + 2) % 3);
            const uint32_t st = sb + (c % 3) * PSTAGE_QK;
            const uint32_t Ah = st, Al = st + PA_TILE;
            const uint32_t Bh = st + 2*PA_TILE, Bl = st + 3*PA_TILE;

#pragma unroll
            for (int kc = 0; kc < 4; kc++) {
                const uint32_t kB = kc * 32;
                uint32_t ah[2][4], al[2][4], bh[4][4], bl[4][4];
#pragma unroll
                for (int ni = 0; ni < 4; ni++) {
                    LDSM4(bh[ni], Bh + swz(bBase + ni * 2048 + kB));
                    LDSM4(bl[ni], Bl + swz(bBase + ni * 2048 + kB));
                }
#pragma unroll
                for (int mi = 0; mi < 2; mi++)
                    LDSM4(ah[mi], Ah + swz(aBase + mi * 2048 + kB));
                // per (mi,ni): hh then hl (matches r10 order)
#pragma unroll
                for (int mi = 0; mi < 2; mi++)
#pragma unroll
                    for (int ni = 0; ni < 4; ni++) {
                        MMA_BF16(acc[mi][2*ni],   ah[mi], bh[ni][0], bh[ni][1]);
                        MMA_BF16(acc[mi][2*ni+1], ah[mi], bh[ni][2], bh[ni][3]);
                        MMA_BF16(acc[mi][2*ni],   ah[mi], bl[ni][0], bl[ni][1]);
                        MMA_BF16(acc[mi][2*ni+1], ah[mi], bl[ni][2], bl[ni][3]);
                    }
                // lh pass
#pragma unroll
                for (int mi = 0; mi < 2; mi++)
                    LDSM4(al[mi], Al + swz(aBase + mi * 2048 + kB));
#pragma unroll
                for (int mi = 0; mi < 2; mi++)
#pragma unroll
                    for (int ni = 0; ni < 4; ni++) {
                        MMA_BF16(acc[mi][2*ni],   al[mi], bh[ni][0], bh[ni][1]);
                        MMA_BF16(acc[mi][2*ni+1], al[mi], bh[ni][2], bh[ni][3]);
                    }
            }
        }
        __syncthreads();

        float* Cs = (float*)smem;            // [128][132]
#pragma unroll
        for (int mi = 0; mi < 2; mi++)
#pragma unroll
            for (int nf = 0; nf < 8; nf++) {
                const int r0 = wm * 32 + mi * 16 + (lane >> 2);
                const int col = wn * 64 + nf * 8 + (lane & 3) * 2;
                *(float2*)&Cs[r0 * 132 + col]       = make_float2(acc[mi][nf][0], acc[mi][nf][1]);
                *(float2*)&Cs[(r0 + 8) * 132 + col] = make_float2(acc[mi][nf][2], acc[mi][nf][3]);
            }
        __syncthreads();

#pragma unroll
        for (int it = 0; it < 16; it++) {
            const int lin = it * 256 + tid;      // 4096 float4 slots
            const int rr = lin >> 5;
            const int cg = (lin & 31) * 4;
            float4 v = *(const float4*)&Cs[rr * 132 + cg];
            const int m = by * 128 + rr;
            const int n = bx * 128 + cg;
            const int b = m >> 11, s = m & 2047, h = n >> 6, d = n & 63;
            __nv_bfloat16* dh = (z == 0) ? g_Qhi : g_Khi;
            __nv_bfloat16* dl = (z == 0) ? g_Qlo : g_Klo;
            uint32_t u0 = packbf2(v.x, v.y), u1 = packbf2(v.z, v.w);
            uint32_t l0 = packbf2(v.x - bflo(u0), v.y - bfhi(u0));
            uint32_t l1 = packbf2(v.z - bflo(u1), v.w - bfhi(u1));
            size_t addr = (((size_t)(b * NH + h)) * SEQ + s) * DH + d;
            *(uint2*)&dh[addr] = make_uint2(u0, u1);
            *(uint2*)&dl[addr] = make_uint2(l0, l1);
        }
    } else {
        // ---------------- V single-f16 path ----------------
        const int j = blockIdx.x - 512;
        const int bx = j & 7, by = j >> 3;          // by 0..31
        const __half* Bf = g_Wf;                     // Wv

        auto load_stage = [&](int c, int slot) {
            const int k0 = c * 64;
            const uint32_t st = sb + slot * PSTAGE_V;
#pragma unroll
            for (int i = 0; i < 4; i++) {
                const int rr = i * 32 + lrow;
                const uint32_t d = swz(rr * 128 + lseg * 16);
                CP_ASYNC16(st + d,
                           g_Xf + (size_t)(by * 128 + rr) * EMB + k0 + lseg * 8);
                CP_ASYNC16(st + PA_TILE + d,
                           Bf + (size_t)(bx * 128 + rr) * EMB + k0 + lseg * 8);
            }
            CP_COMMIT();
        };

        load_stage(0, 0);
        load_stage(1, 1);

        for (int c = 0; c < 16; c++) {
            CP_WAIT1();
            __syncthreads();
            if (c + 2 < 16) load_stage(c + 2, (c + 2) % 3);
            const uint32_t st = sb + (c % 3) * PSTAGE_V;
            const uint32_t At = st, Bt = st + PA_TILE;

#pragma unroll
            for (int kc = 0; kc < 4; kc++) {
                const uint32_t kB = kc * 32;
                uint32_t ar[2][4], bh[4][4];
#pragma unroll
                for (int ni = 0; ni < 4; ni++)
                    LDSM4(bh[ni], Bt + swz(bBase + ni * 2048 + kB));
#pragma unroll
                for (int mi = 0; mi < 2; mi++)
                    LDSM4(ar[mi], At + swz(aBase + mi * 2048 + kB));
#pragma unroll
                for (int mi = 0; mi < 2; mi++)
#pragma unroll
                    for (int ni = 0; ni < 4; ni++) {
                        MMA_F16(acc[mi][2*ni],   ar[mi], bh[ni][0], bh[ni][1]);
                        MMA_F16(acc[mi][2*ni+1], ar[mi], bh[ni][2], bh[ni][3]);
                    }
            }
        }
        __syncthreads();

        float* Cs = (float*)smem;            // [128][132]
#pragma unroll
        for (int mi = 0; mi < 2; mi++)
#pragma unroll
            for (int nf = 0; nf < 8; nf++) {
                const int r0 = wm * 32 + mi * 16 + (lane >> 2);
                const int col = wn * 64 + nf * 8 + (lane & 3) * 2;
                *(float2*)&Cs[r0 * 132 + col]       = make_float2(acc[mi][nf][0], acc[mi][nf][1]);
                *(float2*)&Cs[(r0 + 8) * 132 + col] = make_float2(acc[mi][nf][2], acc[mi][nf][3]);
            }
        __syncthreads();

#pragma unroll
        for (int it = 0; it < 16; it++) {
            const int lin = it * 256 + tid;
            const int rr = lin >> 5;
            const int cg = (lin & 31) * 4;
            float4 v = *(const float4*)&Cs[rr * 132 + cg];
            const int m = by * 128 + rr;
            const int n = bx * 128 + cg;
            const int b = m >> 11, s = m & 2047, h = n >> 6, d = n & 63;
            size_t addr = (((size_t)(b * NH + h)) * SEQ + s) * DH + d;
            *(uint2*)&g_Vf[addr] = make_uint2(packh2(v.x, v.y), packh2(v.z, v.w));
        }
    }
}

// ---------------------------------------------------------------------------
// gemm_o: single-f16 GEMM, O = Of * Wo -> fp32 out. CTA 128x128, 256 thr,
// BK=64, SW128 layout, 3-stage (96KB -> 2 CTAs/SM).
// ---------------------------------------------------------------------------
#define GO_STAGE (2*PA_TILE)             // 32768
#define GO_SMEM  (3*GO_STAGE)            // 98304

__global__ __launch_bounds__(256, 2)
void gemm_o(float* __restrict__ Cout)
{
    extern __shared__ __align__(128) char smem[];
    const uint32_t sb = smem_u32(smem);
    const int tid = threadIdx.x, lane = tid & 31, wid = tid >> 5;
    const int wm = wid & 3, wn = wid >> 2;
    const int bx = blockIdx.x, by = blockIdx.y;   // bx 0..7, by 0..31

    const __half* Bf = g_Wf + (size_t)EMB * EMB;   // Wo

    const uint32_t aBase = (wm * 32 + (lane & 15)) * 128 + (lane >> 4) * 16;
    const uint32_t bBase = (wn * 64 + (lane & 7) + ((lane >> 4) << 3)) * 128
                         + ((lane >> 3) & 1) * 16;
    const int lrow = tid >> 3;
    const int lseg = tid & 7;

    float acc[2][8][4];
#pragma unroll
    for (int i = 0; i < 2; i++)
#pragma unroll
        for (int j = 0; j < 8; j++)
#pragma unroll
            for (int q = 0; q < 4; q++) acc[i][j][q] = 0.0f;

    auto load_stage = [&](int c, int slot) {
        const int k0 = c * 64;
        const uint32_t st = sb + slot * GO_STAGE;
#pragma unroll
        for (int i = 0; i < 4; i++) {
            const int rr = i * 32 + lrow;
            const uint32_t d = swz(rr * 128 + lseg * 16);
            CP_ASYNC16(st + d,
                       g_Of + (size_t)(by * 128 + rr) * EMB + k0 + lseg * 8);
            CP_ASYNC16(st + PA_TILE + d,
                       Bf + (size_t)(bx * 128 + rr) * EMB + k0 + lseg * 8);
        }
        CP_COMMIT();
    };

    load_stage(0, 0);
    load_stage(1, 1);

    for (int c = 0; c < 16; c++) {
        CP_WAIT1();
        __syncthreads();
        if (c + 2 < 16) load_stage(c + 2, (c + 2) % 3);
        const uint32_t st = sb + (c % 3) * GO_STAGE;
        const uint32_t At = st, Bt = st + PA_TILE;

#pragma unroll
        for (int kc = 0; kc < 4; kc++) {
            const uint32_t kB = kc * 32;
            uint32_t ar[2][4], bh[4][4];
#pragma unroll
            for (int ni = 0; ni < 4; ni++)
                LDSM4(bh[ni], Bt + swz(bBase + ni * 2048 + kB));
#pragma unroll
            for (int mi = 0; mi < 2; mi++)
                LDSM4(ar[mi], At + swz(aBase + mi * 2048 + kB));
#pragma unroll
            for (int mi = 0; mi < 2; mi++)
#pragma unroll
                for (int ni = 0; ni < 4; ni++) {
                    MMA_F16(acc[mi][2*ni],   ar[mi], bh[ni][0], bh[ni][1]);
                    MMA_F16(acc[mi][2*ni+1], ar[mi], bh[ni][2], bh[ni][3]);
                }
        }
    }
    __syncthreads();

    float* Cs = (float*)smem;            // [128][132]
#pragma unroll
    for (int mi = 0; mi < 2; mi++)
#pragma unroll
        for (int nf = 0; nf < 8; nf++) {
            const int r0 = wm * 32 + mi * 16 + (lane >> 2);
            const int col = wn * 64 + nf * 8 + (lane & 3) * 2;
            *(float2*)&Cs[r0 * 132 + col]       = make_float2(acc[mi][nf][0], acc[mi][nf][1]);
            *(float2*)&Cs[(r0 + 8) * 132 + col] = make_float2(acc[mi][nf][2], acc[mi][nf][3]);
        }
    __syncthreads();

#pragma unroll
    for (int it = 0; it < 16; it++) {
        const int lin = it * 256 + tid;
        const int rr = lin >> 5;
        const int cg = (lin & 31) * 4;
        float4 v = *(const float4*)&Cs[rr * 132 + cg];
        const int m = by * 128 + rr;
        const int n = bx * 128 + cg;
        *(float4*)&Cout[(size_t)m * EMB + n] = v;
    }
}

// ---------------------------------------------------------------------------
// Flash attention: QK bf16x3, PV f16 P x f16 V (unchanged — known good).
// ---------------------------------------------------------------------------
#define KV_STAGE 49152      // Kh 16KB + Kl 16KB + Vf 16KB
#define FL_SMEM (32768 + 2*KV_STAGE)   // 131072
#define CEXP 0.18033688f    // 0.125 * log2(e)

__global__ __launch_bounds__(256, 1)
void flash_mma()
{
    const int qi = (int)gridDim.x - 1 - blockIdx.x;   // heavy tiles first
    const int h = blockIdx.y, b = blockIdx.z;
    const int tid = threadIdx.x, lane = tid & 31, w = tid >> 5;
    extern __shared__ __align__(128) char smf[];
    const uint32_t sb = smem_u32(smf);
    const uint32_t Qh_ = sb, Ql_ = sb + 16384;

    const size_t head = ((size_t)(b * NH + h)) * SEQ * DH;
    const __nv_bfloat16* Qhg = g_Qhi + head;
    const __nv_bfloat16* Qlg = g_Qlo + head;
    const __nv_bfloat16* Khg = g_Khi + head;
    const __nv_bfloat16* Klg = g_Klo + head;
    const __half*        Vfg = g_Vf  + head;
    const int qbase = qi * 128;

#pragma unroll
    for (int i = 0; i < 4; i++) {
        int lin = i * 256 + tid;
        int r = lin >> 3, c = lin & 7;
        uint32_t off = swz(r * 128 + c * 16);
        CP_ASYNC16(Qh_ + off, Qhg + (size_t)(qbase + r) * 64 + c * 8);
        CP_ASYNC16(Ql_ + off, Qlg + (size_t)(qbase + r) * 64 + c * 8);
    }
    CP_COMMIT();

    auto load_kv = [&](int jt, int slot) {
        const uint32_t st = sb + 32768 + slot * KV_STAGE;
#pragma unroll
        for (int i = 0; i < 4; i++) {
            int lin = i * 256 + tid;
            int r = lin >> 3, c = lin & 7;
            uint32_t off = swz(r * 128 + c * 16);
            size_t gidx = (size_t)(jt * 128 + r) * 64 + c * 8;
            CP_ASYNC16(st + off,             Khg + gidx);
            CP_ASYNC16(st + 16384 + off,     Klg + gidx);
            CP_ASYNC16(st + 32768 + off,     Vfg + gidx);
        }
        CP_COMMIT();
    };

    load_kv(0, 0);
    CP_WAIT1();
    __syncthreads();

    uint32_t qh[4][4], ql[4][4];
    const uint32_t qoff = (w * 16 + (lane & 15)) * 128 + (lane >> 4) * 16;
#pragma unroll
    for (int kc = 0; kc < 4; kc++) {
        LDSM4(qh[kc], Qh_ + swz(qoff + kc * 32));
        LDSM4(ql[kc], Ql_ + swz(qoff + kc * 32));
    }

    float o_[8][4];
#pragma unroll
    for (int i = 0; i < 8; i++)
#pragma unroll
        for (int j = 0; j < 4; j++) o_[i][j] = 0.0f;
    float mrow[2] = {-3e38f, -3e38f};
    float lrow[2] = {0.0f, 0.0f};

    const int rA = qbase + w * 16 + (lane >> 2);
    const int rB = rA + 8;
    const uint32_t kOffBase = ((lane & 7) + ((lane >> 4) << 3)) * 128 + ((lane >> 3) & 1) * 16;
    const uint32_t vOffBase = (lane & 15) * 128 + (lane >> 4) * 16;

    for (int jt = 0; jt <= qi; jt++) {
        CP_WAIT0();
        __syncthreads();
        if (jt < qi) load_kv(jt + 1, (jt + 1) & 1);
        const uint32_t st = sb + 32768 + (jt & 1) * KV_STAGE;
        const uint32_t Kh_ = st, Kl_ = st + 16384, Vf_ = st + 32768;

        float s_[16][4];
#pragma unroll
        for (int i = 0; i < 16; i++)
#pragma unroll
            for (int j = 0; j < 4; j++) s_[i][j] = 0.0f;

#pragma unroll
        for (int tp = 0; tp < 4; tp++) {
#pragma unroll
            for (int kc = 0; kc < 4; kc++) {
                const uint32_t addrA = swz((2*tp)   * 16 * 128 + kOffBase + kc * 32);
                const uint32_t addrB = swz((2*tp+1) * 16 * 128 + kOffBase + kc * 32);
                uint32_t bha[4], bla[4], bhb[4], blb[4];
                LDSM4(bha, Kh_ + addrA);
                LDSM4(bhb, Kh_ + addrB);
                LDSM4(bla, Kl_ + addrA);
                LDSM4(blb, Kl_ + addrB);
                MMA_BF16(s_[4*tp],     qh[kc], bha[0], bha[1]);
                MMA_BF16(s_[4*tp + 1], qh[kc], bha[2], bha[3]);
                MMA_BF16(s_[4*tp + 2], qh[kc], bhb[0], bhb[1]);
                MMA_BF16(s_[4*tp + 3], qh[kc], bhb[2], bhb[3]);
                MMA_BF16(s_[4*tp],     ql[kc], bha[0], bha[1]);
                MMA_BF16(s_[4*tp + 1], ql[kc], bha[2], bha[3]);
                MMA_BF16(s_[4*tp + 2], ql[kc], bhb[0], bhb[1]);
                MMA_BF16(s_[4*tp + 3], ql[kc], bhb[2], bhb[3]);
                MMA_BF16(s_[4*tp],     qh[kc], bla[0], bla[1]);
                MMA_BF16(s_[4*tp + 1], qh[kc], bla[2], bla[3]);
                MMA_BF16(s_[4*tp + 2], qh[kc], blb[0], blb[1]);
                MMA_BF16(s_[4*tp + 3], qh[kc], blb[2], blb[3]);
            }
        }

        if (jt == qi) {
#pragma unroll
            for (int nf = 0; nf < 16; nf++) {
                const int colg = jt * 128 + nf * 8 + (lane & 3) * 2;
                if (colg     > rA) s_[nf][0] = -3e38f;
                if (colg + 1 > rA) s_[nf][1] = -3e38f;
                if (colg     > rB) s_[nf][2] = -3e38f;
                if (colg + 1 > rB) s_[nf][3] = -3e38f;
            }
        }

        float mx0 = -3e38f, mx1 = -3e38f;
#pragma unroll
        for (int nf = 0; nf < 16; nf++) {
            mx0 = fmaxf(mx0, fmaxf(s_[nf][0], s_[nf][1]));
            mx1 = fmaxf(mx1, fmaxf(s_[nf][2], s_[nf][3]));
        }
        mx0 = fmaxf(mx0, __shfl_xor_sync(0xffffffffu, mx0, 1));
        mx0 = fmaxf(mx0, __shfl_xor_sync(0xffffffffu, mx0, 2));
        mx1 = fmaxf(mx1, __shfl_xor_sync(0xffffffffu, mx1, 1));
        mx1 = fmaxf(mx1, __shfl_xor_sync(0xffffffffu, mx1, 2));
        const float mn0 = fmaxf(mrow[0], mx0);
        const float mn1 = fmaxf(mrow[1], mx1);
        const float c0 = fast_exp2((mrow[0] - mn0) * CEXP);
        const float c1 = fast_exp2((mrow[1] - mn1) * CEXP);
        mrow[0] = mn0; mrow[1] = mn1;

        uint32_t ph[8][4];
        float rs0 = 0.0f, rs1 = 0.0f;
#pragma unroll
        for (int j = 0; j < 8; j++) {
            const float p00 = fast_exp2((s_[2*j][0]   - mn0) * CEXP);
            const float p01 = fast_exp2((s_[2*j][1]   - mn0) * CEXP);
            const float p10 = fast_exp2((s_[2*j][2]   - mn1) * CEXP);
            const float p11 = fast_exp2((s_[2*j][3]   - mn1) * CEXP);
            const float p20 = fast_exp2((s_[2*j+1][0] - mn0) * CEXP);
            const float p21 = fast_exp2((s_[2*j+1][1] - mn0) * CEXP);
            const float p30 = fast_exp2((s_[2*j+1][2] - mn1) * CEXP);
            const float p31 = fast_exp2((s_[2*j+1][3] - mn1) * CEXP);
            ph[j][0] = packh2(p00, p01);
            ph[j][1] = packh2(p10, p11);
            ph[j][2] = packh2(p20, p21);
            ph[j][3] = packh2(p30, p31);
            rs0 += hsum2(ph[j][0]) + hsum2(ph[j][2]);
            rs1 += hsum2(ph[j][1]) + hsum2(ph[j][3]);
        }
        rs0 += __shfl_xor_sync(0xffffffffu, rs0, 1);
        rs0 += __shfl_xor_sync(0xffffffffu, rs0, 2);
        rs1 += __shfl_xor_sync(0xffffffffu, rs1, 1);
        rs1 += __shfl_xor_sync(0xffffffffu, rs1, 2);
        lrow[0] = lrow[0] * c0 + rs0;
        lrow[1] = lrow[1] * c1 + rs1;
#pragma unroll
        for (int nf = 0; nf < 8; nf++) {
            o_[nf][0] *= c0; o_[nf][1] *= c0;
            o_[nf][2] *= c1; o_[nf][3] *= c1;
        }

#pragma unroll
        for (int j = 0; j < 8; j++) {
#pragma unroll
            for (int t = 0; t < 4; t++) {
                uint32_t vf[4];
                LDSM4T(vf, Vf_ + swz(j * 16 * 128 + vOffBase + t * 32));
                MMA_F16(o_[2 * t],     ph[j], vf[0], vf[1]);
                MMA_F16(o_[2 * t + 1], ph[j], vf[2], vf[3]);
            }
        }
    }

    const float iA = 1.0f / lrow[0];
    const float iB = 1.0f / lrow[1];
    const size_t rowA = (size_t)(b * SEQ + rA) * EMB + h * 64;
    const size_t rowB = (size_t)(b * SEQ + rB) * EMB + h * 64;
#pragma unroll
    for (int nf = 0; nf < 8; nf++) {
        const int d = nf * 8 + (lane & 3) * 2;
        *(uint32_t*)&g_Of[rowA + d] = packh2(o_[nf][0] * iA, o_[nf][1] * iA);
        *(uint32_t*)&g_Of[rowB + d] = packh2(o_[nf][2] * iB, o_[nf][3] * iB);
    }
}

// ---------------------------------------------------------------------------
extern "C" void kernel_launch(void* const* d_in, const int* in_sizes, int n_in,
                              void* d_out, int out_size)
{
    const float* x  = (const float*)d_in[0];
    const float* Wq = (const float*)d_in[1];
    const float* Wk = (const float*)d_in[2];
    const float* Wv = (const float*)d_in[3];
    const float* Wo = (const float*)d_in[4];
    float* out = (float*)d_out;

    cudaFuncSetAttribute(proj_all,
                         cudaFuncAttributeMaxDynamicSharedMemorySize, PROJ_SMEM);
    cudaFuncSetAttribute(gemm_o,
                         cudaFuncAttributeMaxDynamicSharedMemorySize, GO_SMEM);
    cudaFuncSetAttribute(flash_mma,
                         cudaFuncAttributeMaxDynamicSharedMemorySize, FL_SMEM);

    // Convert X (bf16 hi/lo + f16) and W (Wq/Wk bf16 hi/lo, Wv/Wo f16)
    convert_all<<<2560, 256>>>(x, Wq, Wk, Wv, Wo);

    // Q,K (bf16x3) + V (f16) projections, conflict-free SW128 smem
    proj_all<<<768, 256, PROJ_SMEM>>>();

    // Flash attention -> Of (f16 row-major)
    flash_mma<<<dim3(SEQ/128, NH, BATCH), 256, FL_SMEM>>>();

    // Output projection (single f16) -> fp32 out
    gemm_o<<<dim3(8, 32), 256, GO_SMEM>>>(out);
}